// round 14
// baseline (speedup 1.0000x reference)
#include <cuda_runtime.h>
#include <cuda_bf16.h>
#include <math.h>

// Problem constants (fixed instance)
#define BB 2
#define NN 2048
#define FEMB 16
#define FFEAT 2
#define FIN 18
#define EE 64
#define HH 2
#define KK 2
#define HID 64
#define BN (BB*NN)
#define FLOW_GRID 512

// ---------------- scratch (static device globals; no runtime allocation) ----------------
__device__ float g_h[BN*EE];                 // node hidden state
__device__ float g_z[HH*BN*EE];              // per-head projected features (fp32, for zmean path)
__device__ __align__(16) __nv_bfloat16 g_zb[HH*BN*EE];  // bf16 copy for gather traffic
__device__ float g_ssrc[HH*BN];
__device__ float g_sdst[HH*BN];
__device__ float g_zmean[HH*BB*EE];          // fallback for empty neighbor rows
__device__ float g_aggp[HH*BN*KK*EE];        // per-head aggregation partials
__device__ int   g_rowptr[KK*BN];
__device__ int   g_deg[KK*BN];
__device__ int   g_col[KK*BN*NN];            // CSR col indices, fixed row*NN bases
__device__ float g_nw[BN];                   // decoder node weights
__device__ float g_dv[BN];                   // dual vars
__device__ float g_eprop[BN*NN];             // per-edge prop value (k=0 edge index space)
__device__ int   g_erecip[BN*NN];            // reciprocal edge index or -1
__device__ int   g_indeg[BN];
__device__ int   g_cscPtr[BN+1];
__device__ int   g_cscFill[BN];
__device__ int   g_cscSrc[BN*NN];            // src global row per in-edge
__device__ int   g_cscEdge[BN*NN];           // edge index per in-edge
__device__ float g_s0[BN], g_s1[BN];         // flow scalar ping-pong
__device__ float g_emptyArr[10*BB];          // uniform-mass scalar per iteration input
__device__ double g_accflow[BB], g_accdual[BB];

// software grid barrier state (reset by k_encoder each replay)
__device__ unsigned g_barCnt;
__device__ volatile unsigned g_barPhase;

// CG-style grid sync: syncthreads -> leader release-fence + arrive/spin -> acquire-fence -> syncthreads.
// phase values must be strictly increasing within a launch, and distinct across kernels in one replay.
__device__ __forceinline__ void grid_barrier(unsigned phase) {
    __syncthreads();
    if (threadIdx.x == 0) {
        __threadfence();
        if (atomicAdd(&g_barCnt, 1u) == gridDim.x - 1) {
            g_barCnt = 0;
            __threadfence();
            g_barPhase = phase;
        } else {
            while (g_barPhase < phase) {}
        }
        __threadfence();
    }
    __syncthreads();
}

// ---------------------------------------------------------------------------------------
// encoder: h = tanh(tanh([emb,feat]@W0+b0)@W1+b1), one block (64 thr) per node.
// Also performs all per-replay zero-initialization (replaces k_init).
__global__ void k_encoder(const float* __restrict__ emb, const float* __restrict__ feat,
                          const float* __restrict__ W0, const float* __restrict__ b0,
                          const float* __restrict__ W1, const float* __restrict__ b1) {
    int node = blockIdx.x;
    int e = threadIdx.x;
    if (e == 0) { g_indeg[node] = 0; g_cscFill[node] = 0; }
    if (node == 0) {
        g_zmean[e] = 0.f; g_zmean[64 + e] = 0.f;
        g_zmean[128 + e] = 0.f; g_zmean[192 + e] = 0.f;
        if (e < 10*BB) g_emptyArr[e] = 0.f;
        if (e < BB) { g_accflow[e] = 0.0; g_accdual[e] = 0.0; }
        if (e == 0) { g_barCnt = 0; g_barPhase = 0; }
    }
    __shared__ float x[FIN];
    __shared__ float h0[HID];
    if (e < FEMB) x[e] = emb[node*FEMB + e];
    else if (e < FIN) x[e] = feat[node*FFEAT + (e - FEMB)];
    __syncthreads();
    float acc = b0[e];
#pragma unroll
    for (int f = 0; f < FIN; f++) acc = fmaf(x[f], W0[f*HID + e], acc);
    h0[e] = tanhf(acc);
    __syncthreads();
    float a0 = b1[e], a1 = 0.f;
#pragma unroll 8
    for (int f = 0; f < HID; f += 2) {
        a0 = fmaf(h0[f],     W1[f*EE + e],       a0);
        a1 = fmaf(h0[f + 1], W1[(f + 1)*EE + e], a1);
    }
    g_h[node*EE + e] = tanhf(a0 + a1);
}

// CSR build: single pass, fixed row bases (no compaction across rows, no atomics).
__global__ void k_build_csr(const float* __restrict__ nbh) {
    int wrow = blockIdx.x * (blockDim.x >> 5) + (threadIdx.x >> 5);
    int lane = threadIdx.x & 31;
    if (wrow >= KK*BN) return;
    const float* row = nbh + (size_t)wrow * NN;
    int rbase = wrow * NN;
    unsigned lt = (1u << lane) - 1u;
    int off = 0;
#pragma unroll 4
    for (int j0 = 0; j0 < NN; j0 += 128) {
        float v0 = row[j0 + lane];
        float v1 = row[j0 + 32 + lane];
        float v2 = row[j0 + 64 + lane];
        float v3 = row[j0 + 96 + lane];
        unsigned b0 = __ballot_sync(0xffffffffu, v0 > 0.f);
        if (v0 > 0.f) g_col[rbase + off + __popc(b0 & lt)] = j0 + lane;
        off += __popc(b0);
        unsigned b1 = __ballot_sync(0xffffffffu, v1 > 0.f);
        if (v1 > 0.f) g_col[rbase + off + __popc(b1 & lt)] = j0 + 32 + lane;
        off += __popc(b1);
        unsigned b2 = __ballot_sync(0xffffffffu, v2 > 0.f);
        if (v2 > 0.f) g_col[rbase + off + __popc(b2 & lt)] = j0 + 64 + lane;
        off += __popc(b2);
        unsigned b3 = __ballot_sync(0xffffffffu, v3 > 0.f);
        if (v3 > 0.f) g_col[rbase + off + __popc(b3 & lt)] = j0 + 96 + lane;
        off += __popc(b3);
    }
    if (lane == 0) { g_rowptr[wrow] = rbase; g_deg[wrow] = off; }
}

// ===== fused graph preprocessing: recip+indeg -> scan -> cscfill, one launch =====
// grid = FLOW_GRID x 256 (4096 warps == BN rows), grid barriers between phases.
__global__ void __launch_bounds__(256) k_graph() {
    int gw = (blockIdx.x * 256 + threadIdx.x) >> 5;   // global warp == k=0 row
    int lane = threadIdx.x & 31;
    int b = gw / NN;
    int n = gw - b*NN;
    int rbase = g_rowptr[gw];
    int deg = g_deg[gw];

    // phase 1: reciprocal edge index (binary search) + in-degree count
    for (int idx = lane; idx < deg; idx += 32) {
        int j = g_col[rbase + idx];
        int jr = b*NN + j;
        int jb = g_rowptr[jr], dj = g_deg[jr];
        int lo = 0, hi = dj;
        while (lo < hi) { int mid = (lo + hi) >> 1; if (g_col[jb + mid] < n) lo = mid + 1; else hi = mid; }
        g_erecip[rbase + idx] = (lo < dj && g_col[jb + lo] == n) ? (jb + lo) : -1;
        atomicAdd(&g_indeg[jr], 1);
    }
    grid_barrier(1);

    // phase 2: exclusive scan of indeg by block 0 (256 thr x 16 elems)
    if (blockIdx.x == 0) {
        __shared__ int ssum[256];
        int t = threadIdx.x;
        int base = t * 16;
        int v[16];
        int s = 0;
#pragma unroll
        for (int i = 0; i < 16; i++) { v[i] = s; s += g_indeg[base + i]; }
        ssum[t] = s; __syncthreads();
        for (int off = 1; off < 256; off <<= 1) {
            int x = (t >= off) ? ssum[t - off] : 0;
            __syncthreads();
            ssum[t] += x;
            __syncthreads();
        }
        int pre = (t == 0) ? 0 : ssum[t - 1];
#pragma unroll
        for (int i = 0; i < 16; i++) g_cscPtr[base + i] = pre + v[i];
        if (t == 255) g_cscPtr[BN] = ssum[255];
    }
    grid_barrier(2);

    // phase 3: CSC fill
    for (int idx = lane; idx < deg; idx += 32) {
        int dst = b*NN + g_col[rbase + idx];
        int pos = g_cscPtr[dst] + atomicAdd(&g_cscFill[dst], 1);
        g_cscSrc[pos] = gw;
        g_cscEdge[pos] = rbase + idx;
    }
}

// z = h @ attn_W per head; s_src/s_dst row scores; zmean accumulation fused (REDG).
__global__ void k_z(const float* __restrict__ attn_W, const float* __restrict__ a_src,
                    const float* __restrict__ a_dst) {
    int node = blockIdx.x;
    int t = threadIdx.x;
    int head = t >> 6, e = t & 63;
    int b = node / NN;
    __shared__ float hs[EE];
    __shared__ float rs[2], rd[2];
    if (t < EE) hs[t] = g_h[node*EE + t];
    if (t < 2) { rs[t] = 0.f; rd[t] = 0.f; }
    __syncthreads();
    const float* W = attn_W + head*EE*EE;
    float a0 = 0.f, a1 = 0.f, a2 = 0.f, a3 = 0.f;
#pragma unroll 4
    for (int d = 0; d < EE; d += 4) {
        a0 = fmaf(hs[d],     W[d*EE + e],       a0);
        a1 = fmaf(hs[d + 1], W[(d + 1)*EE + e], a1);
        a2 = fmaf(hs[d + 2], W[(d + 2)*EE + e], a2);
        a3 = fmaf(hs[d + 3], W[(d + 3)*EE + e], a3);
    }
    float acc = (a0 + a1) + (a2 + a3);
    size_t zi = ((size_t)head*BN + node)*EE + e;
    g_z[zi] = acc;
    g_zb[zi] = __float2bfloat16(acc);
    atomicAdd(&g_zmean[(head*BB + b)*EE + e], acc * (1.0f / NN));
    float vs = acc * a_src[head*EE + e];
    float vd = acc * a_dst[head*EE + e];
#pragma unroll
    for (int o = 16; o > 0; o >>= 1) {
        vs += __shfl_xor_sync(0xffffffffu, vs, o);
        vd += __shfl_xor_sync(0xffffffffu, vd, o);
    }
    if ((t & 31) == 0) { atomicAdd(&rs[head], vs); atomicAdd(&rd[head], vd); }
    __syncthreads();
    if (t < 2) { g_ssrc[t*BN + node] = rs[t]; g_sdst[t*BN + node] = rd[t]; }
}

// sparse attention aggregation: one warp per (head,k,node). bf16x2 gathers, fp32 accumulate.
__global__ void k_agg() {
    int warp = blockIdx.x * (blockDim.x >> 5) + (threadIdx.x >> 5);
    int lane = threadIdx.x & 31;
    if (warp >= HH*KK*BN) return;
    int head = warp / (KK*BN);
    int rem = warp - head*(KK*BN);
    int k = rem / BN;
    int node = rem - k*BN;
    int b = node / NN;
    float ss = g_ssrc[head*BN + node];
    const float* sd = g_sdst + head*BN + b*NN;
    const __nv_bfloat162* z =
        reinterpret_cast<const __nv_bfloat162*>(g_zb + ((size_t)head*BN + (size_t)b*NN)*EE);
    int crow = k*BN + node;
    int rbase = g_rowptr[crow];
    int deg = g_deg[crow];
    float accx = 0.f, accy = 0.f, Z = 0.f;
    for (int i0 = 0; i0 < deg; i0 += 32) {
        int idx = i0 + lane;
        int m = (idx < deg) ? __ldg(&g_col[rbase + idx]) : -1;
        float w = (m >= 0) ? expf(tanhf(ss + sd[m])) : 0.f;
        float r = w;
#pragma unroll
        for (int o = 16; o > 0; o >>= 1) r += __shfl_xor_sync(0xffffffffu, r, o);
        Z += r;
        int cnt = deg - i0; if (cnt > 32) cnt = 32;
#pragma unroll 4
        for (int j = 0; j < cnt; j++) {
            int   mj = __shfl_sync(0xffffffffu, m, j);
            float wj = __shfl_sync(0xffffffffu, w, j);
            float2 v = __bfloat1622float2(__ldg(&z[mj*32 + lane]));
            accx = fmaf(wj, v.x, accx);
            accy = fmaf(wj, v.y, accy);
        }
    }
    float2 outv;
    if (deg > 0) {
        float inv = 1.f / Z;
        outv.x = accx * inv; outv.y = accy * inv;
    } else {
        outv.x = g_zmean[(head*BB + b)*EE + 2*lane];
        outv.y = g_zmean[(head*BB + b)*EE + 2*lane + 1];
    }
    float2* dst = (float2*)(g_aggp + (((size_t)head*BN + node)*KK + k)*EE);
    dst[lane] = outv;
}

// combine heads + neighborhood attention over k + GRU update. block (64 thr) per node.
// also re-zeroes g_zmean (block 0) for the next layer.
__global__ void k_update(const float* __restrict__ nbr_q, const float* __restrict__ gru_W,
                         const float* __restrict__ gru_U, const float* __restrict__ gru_b) {
    int node = blockIdx.x;
    int e = threadIdx.x;
    __shared__ float a0[EE], a1[EE], hs[EE], nxt[EE], rh[EE];
    __shared__ float red[2];
    size_t i00 = (((size_t)0*BN + node)*KK + 0)*EE + e;
    size_t i01 = (((size_t)0*BN + node)*KK + 1)*EE + e;
    size_t i10 = (((size_t)1*BN + node)*KK + 0)*EE + e;
    size_t i11 = (((size_t)1*BN + node)*KK + 1)*EE + e;
    a0[e] = tanhf(0.5f*(g_aggp[i00] + g_aggp[i10]));
    a1[e] = tanhf(0.5f*(g_aggp[i01] + g_aggp[i11]));
    hs[e] = g_h[node*EE + e];
    if (e < 2) red[e] = 0.f;
    if (node == 0) {
        g_zmean[e] = 0.f; g_zmean[64 + e] = 0.f;
        g_zmean[128 + e] = 0.f; g_zmean[192 + e] = 0.f;
    }
    __syncthreads();
    float q = nbr_q[e];
    float v0 = a0[e]*q, v1 = a1[e]*q;
#pragma unroll
    for (int o = 16; o > 0; o >>= 1) {
        v0 += __shfl_xor_sync(0xffffffffu, v0, o);
        v1 += __shfl_xor_sync(0xffffffffu, v1, o);
    }
    if ((e & 31) == 0) { atomicAdd(&red[0], v0); atomicAdd(&red[1], v1); }
    __syncthreads();
    float t0 = tanhf(red[0]), t1 = tanhf(red[1]);
    float e0 = expf(t0), e1 = expf(t1);
    float inv = 1.f / (e0 + e1);
    nxt[e] = e0*inv*a0[e] + e1*inv*a1[e];
    __syncthreads();
    float sW0 = 0.f, sW1 = 0.f, sW2 = 0.f, sU0 = 0.f, sU1 = 0.f;
#pragma unroll 8
    for (int d = 0; d < EE; d++) {
        float nd = nxt[d], hd = hs[d];
        const float* Wr = gru_W + d*192;
        const float* Ur = gru_U + d*192;
        sW0 = fmaf(nd, Wr[e],       sW0);
        sW1 = fmaf(nd, Wr[e + 64],  sW1);
        sW2 = fmaf(nd, Wr[e + 128], sW2);
        sU0 = fmaf(hd, Ur[e],       sU0);
        sU1 = fmaf(hd, Ur[e + 64],  sU1);
    }
    float zg = 1.f / (1.f + expf(-(sW0 + sU0 + gru_b[e])));
    float r  = 1.f / (1.f + expf(-(sW1 + sU1 + gru_b[e + 64])));
    rh[e] = r * hs[e];
    __syncthreads();
    float sU2 = 0.f;
#pragma unroll 8
    for (int d = 0; d < EE; d++) sU2 = fmaf(rh[d], gru_U[d*192 + e + 128], sU2);
    float htl = tanhf(sW2 + sU2 + gru_b[e + 128]);
    g_h[node*EE + e] = (1.f - zg)*hs[e] + zg*htl;
}

// decoder + dual-var MLPs fused. block (64 thr) per node.
__global__ void k_decode(const float* __restrict__ dW0, const float* __restrict__ db0,
                         const float* __restrict__ dW1, const float* __restrict__ db1,
                         const float* __restrict__ uW0, const float* __restrict__ ub0,
                         const float* __restrict__ uW1, const float* __restrict__ ub1) {
    int node = blockIdx.x;
    int e = threadIdx.x;
    __shared__ float hs[EE];
    __shared__ float red[2];
    hs[e] = g_h[node*EE + e];
    if (e < 2) red[e] = 0.f;
    __syncthreads();
    float ad = db0[e], au = ub0[e];
#pragma unroll 8
    for (int d = 0; d < EE; d++) {
        float hd = hs[d];
        ad = fmaf(hd, dW0[d*64 + e], ad);
        au = fmaf(hd, uW0[d*64 + e], au);
    }
    float vd = tanhf(ad) * dW1[e];
    float vu = tanhf(au) * uW1[e];
#pragma unroll
    for (int o = 16; o > 0; o >>= 1) {
        vd += __shfl_xor_sync(0xffffffffu, vd, o);
        vu += __shfl_xor_sync(0xffffffffu, vu, o);
    }
    if ((e & 31) == 0) { atomicAdd(&red[0], vd); atomicAdd(&red[1], vu); }
    __syncthreads();
    if (e == 0) { g_nw[node] = red[0] + db1[0]; g_dv[node] = red[1] + ub1[0]; }
}

// ===== mega-fused flow + dual section with full-grid phases =====
// grid = FLOW_GRID x 256 (4096 warps == rows). Phases separated by grid barriers.
__global__ void __launch_bounds__(256) k_flow(const float* __restrict__ demands,
                                              float* __restrict__ out) {
    int gw = (blockIdx.x * 256 + threadIdx.x) >> 5;   // row
    int lane = threadIdx.x & 31;
    int b = gw / NN;
    int rbase = g_rowptr[gw];
    int deg = g_deg[gw];
    const float* nwb = g_nw + b*NN;

    // ---- phase: per-edge prop (row softmax over neighbors), warp per row ----
    if (deg > 0) {
        float mx = -3.0e38f;
        for (int idx = lane; idx < deg; idx += 32) mx = fmaxf(mx, nwb[g_col[rbase + idx]]);
#pragma unroll
        for (int o = 16; o > 0; o >>= 1) mx = fmaxf(mx, __shfl_xor_sync(0xffffffffu, mx, o));
        float sm = 0.f;
        for (int idx = lane; idx < deg; idx += 32) sm += expf(nwb[g_col[rbase + idx]] - mx);
#pragma unroll
        for (int o = 16; o > 0; o >>= 1) sm += __shfl_xor_sync(0xffffffffu, sm, o);
        float inv = 1.f / sm;
        for (int idx = lane; idx < deg; idx += 32)
            g_eprop[rbase + idx] = expf(nwb[g_col[rbase + idx]] - mx) * inv;
    }
    // ---- s0 = relu(-d); seed uniform mass ----
    if (lane == 0) {
        float v = fmaxf(-demands[gw], 0.f);
        g_s0[gw] = v;
        if (deg == 0 && v != 0.f) atomicAdd(&g_emptyArr[b], v);
    }
    grid_barrier(10);

    // ---- 9 sparse matvec iterations (__ldcg for cross-barrier re-reads) ----
    int p0 = g_cscPtr[gw], p1 = g_cscPtr[gw + 1];
    for (int it = 0; it < 9; it++) {
        const float* sin  = (it & 1) ? g_s1 : g_s0;
        float*       sout = (it & 1) ? g_s0 : g_s1;
        float acc = 0.f;
        for (int q = p0 + lane; q < p1; q += 32)
            acc += g_eprop[g_cscEdge[q]] * __ldcg(&sin[g_cscSrc[q]]);
#pragma unroll
        for (int o = 16; o > 0; o >>= 1) acc += __shfl_xor_sync(0xffffffffu, acc, o);
        if (lane == 0) {
            float uni = __ldcg(&g_emptyArr[it*BB + b]) * (1.0f / NN);
            float sv = fmaxf(acc + uni - demands[gw], 0.f);
            sout[gw] = sv;
            if (deg == 0 && sv != 0.f) atomicAdd(&g_emptyArr[(it + 1)*BB + b], sv);
        }
        grid_barrier(11 + it);
    }

    // ---- fused flow-cost + dual-edge-cost + dual-demand ----
    const float* sfin = g_s1;   // it=8 wrote g_s1
    float si = __ldcg(&sfin[gw]);
    float dvi = g_dv[gw];
    float facc = 0.f, dacc = 0.f;
    for (int idx = lane; idx < deg; idx += 32) {
        int e = rbase + idx;
        int j = g_col[e];
        int jg = b*NN + j;
        float f = g_eprop[e] * si;
        int rc = g_erecip[e];
        float frec = (rc >= 0) ? g_eprop[rc] * __ldcg(&sfin[jg])
                               : ((g_deg[jg] == 0) ? __ldcg(&sfin[jg]) * (1.0f / NN) : 0.f);
        float fl = f - fminf(f, frec);
        facc = fmaf(fl, fl, facc);
        float dd = dvi - g_dv[jg];
        float y = 0.f, m = 0.f;
#pragma unroll
        for (int itr = 0; itr < 10; itr++) {
            float g2 = 2.f*y - dd;
            m = 0.9f*m + g2;
            y = fmaxf(y - 0.1f*m, 0.f);
        }
        dacc += y*y - dd*y;
    }
#pragma unroll
    for (int o = 16; o > 0; o >>= 1) {
        facc += __shfl_xor_sync(0xffffffffu, facc, o);
        dacc += __shfl_xor_sync(0xffffffffu, dacc, o);
    }
    if (lane == 0) {
        if (deg == 0) facc += si * si * (1.0f / NN);  // uniform row: sum_j (s_i/N)^2
        // out = flow_cost - (dual_edge - dual_demand) = (flow + ddem) - dual_edge
        atomicAdd(&g_accflow[b], (double)facc + (double)(dvi * demands[gw]));
        atomicAdd(&g_accdual[b], (double)dacc);
    }
    grid_barrier(30);

    if (blockIdx.x == 0 && threadIdx.x < BB) {
        double f = *((volatile double*)&g_accflow[threadIdx.x]);
        double d = *((volatile double*)&g_accdual[threadIdx.x]);
        out[threadIdx.x] = (float)(f - d);
    }
}

// ---------------------------------------------------------------------------------------
extern "C" void kernel_launch(void* const* d_in, const int* in_sizes, int n_in,
                              void* d_out, int out_size) {
    const float* node_features   = (const float*)d_in[0];
    const float* node_embeddings = (const float*)d_in[1];
    const float* demands = (const float*)d_in[2];
    const float* nbh     = (const float*)d_in[4];
    const float* enc_W0  = (const float*)d_in[5];
    const float* enc_b0  = (const float*)d_in[6];
    const float* enc_W1  = (const float*)d_in[7];
    const float* enc_b1  = (const float*)d_in[8];
    const float* attn_W  = (const float*)d_in[9];
    const float* a_src   = (const float*)d_in[10];
    const float* a_dst   = (const float*)d_in[11];
    const float* nbr_q   = (const float*)d_in[12];
    const float* gru_W   = (const float*)d_in[13];
    const float* gru_U   = (const float*)d_in[14];
    const float* gru_b   = (const float*)d_in[15];
    const float* dec_W0  = (const float*)d_in[16];
    const float* dec_b0  = (const float*)d_in[17];
    const float* dec_W1  = (const float*)d_in[18];
    const float* dec_b1  = (const float*)d_in[19];
    const float* dual_W0 = (const float*)d_in[20];
    const float* dual_b0 = (const float*)d_in[21];
    const float* dual_W1 = (const float*)d_in[22];
    const float* dual_b1 = (const float*)d_in[23];
    float* out = (float*)d_out;

    k_encoder<<<BN, 64>>>(node_embeddings, node_features, enc_W0, enc_b0, enc_W1, enc_b1);
    k_build_csr<<<(KK*BN)/8, 256>>>(nbh);
    k_graph<<<FLOW_GRID, 256>>>();

    for (int layer = 0; layer < 2; layer++) {
        k_z<<<BN, 128>>>(attn_W, a_src, a_dst);
        k_agg<<<(HH*KK*BN)/8, 256>>>();
        k_update<<<BN, 64>>>(nbr_q, gru_W, gru_U, gru_b);
    }

    k_decode<<<BN, 64>>>(dec_W0, dec_b0, dec_W1, dec_b1, dual_W0, dual_b0, dual_W1, dual_b1);
    k_flow<<<FLOW_GRID, 256>>>(demands, out);
}

// round 15
// speedup vs baseline: 1.3076x; 1.3076x over previous
#include <cuda_runtime.h>
#include <cuda_bf16.h>
#include <math.h>

// Problem constants (fixed instance)
#define BB 2
#define NN 2048
#define FEMB 16
#define FFEAT 2
#define FIN 18
#define EE 64
#define HH 2
#define KK 2
#define HID 64
#define BN (BB*NN)
#define FLOW_GRID 512

// ---------------- scratch (static device globals; no runtime allocation) ----------------
__device__ float g_h[BN*EE];                 // node hidden state
__device__ float g_z[HH*BN*EE];              // per-head projected features (fp32, zmean path)
__device__ __align__(16) uint2 g_zp[BN*32];  // packed bf16 z: per node 32x{head0 bf16x2, head1 bf16x2}
__device__ float g_ssrc[HH*BN];
__device__ float g_sdst[HH*BN];
__device__ float g_zmean[HH*BB*EE];          // fallback for empty neighbor rows
__device__ float g_aggp[HH*BN*KK*EE];        // per-head aggregation partials
__device__ int   g_rowptr[KK*BN];
__device__ int   g_deg[KK*BN];
__device__ int   g_col[KK*BN*NN];            // CSR col indices, fixed row*NN bases
__device__ float g_nw[BN];                   // decoder node weights
__device__ float g_dv[BN];                   // dual vars
__device__ float g_eprop[BN*NN];             // per-edge prop value (k=0 edge index space)
__device__ int   g_erecip[BN*NN];            // reciprocal edge index or -1
__device__ int   g_indeg[BN];
__device__ int   g_cscPtr[BN+1];
__device__ int   g_cscFill[BN];
__device__ int   g_cscSrc[BN*NN];            // src global row per in-edge
__device__ int   g_cscEdge[BN*NN];           // edge index per in-edge
__device__ float g_s0[BN], g_s1[BN];         // flow scalar ping-pong
__device__ float g_emptyArr[10*BB];          // uniform-mass scalar per iteration input
__device__ double g_accflow[BB], g_accdual[BB];

// software grid barrier state (reset by k_encoder each replay)
__device__ unsigned g_barCnt;
__device__ volatile unsigned g_barPhase;

__device__ __forceinline__ void grid_barrier(unsigned phase) {
    __syncthreads();
    if (threadIdx.x == 0) {
        __threadfence();
        if (atomicAdd(&g_barCnt, 1u) == gridDim.x - 1) {
            g_barCnt = 0;
            __threadfence();
            g_barPhase = phase;
        } else {
            while (g_barPhase < phase) {}
        }
        __threadfence();
    }
    __syncthreads();
}

// ---------------------------------------------------------------------------------------
// encoder + all per-replay zero-init. one block (64 thr) per node.
__global__ void k_encoder(const float* __restrict__ emb, const float* __restrict__ feat,
                          const float* __restrict__ W0, const float* __restrict__ b0,
                          const float* __restrict__ W1, const float* __restrict__ b1) {
    int node = blockIdx.x;
    int e = threadIdx.x;
    if (e == 0) { g_indeg[node] = 0; g_cscFill[node] = 0; }
    if (node == 0) {
        g_zmean[e] = 0.f; g_zmean[64 + e] = 0.f;
        g_zmean[128 + e] = 0.f; g_zmean[192 + e] = 0.f;
        if (e < 10*BB) g_emptyArr[e] = 0.f;
        if (e < BB) { g_accflow[e] = 0.0; g_accdual[e] = 0.0; }
        if (e == 0) { g_barCnt = 0; g_barPhase = 0; }
    }
    __shared__ float x[FIN];
    __shared__ float h0[HID];
    if (e < FEMB) x[e] = emb[node*FEMB + e];
    else if (e < FIN) x[e] = feat[node*FFEAT + (e - FEMB)];
    __syncthreads();
    float acc = b0[e];
#pragma unroll
    for (int f = 0; f < FIN; f++) acc = fmaf(x[f], W0[f*HID + e], acc);
    h0[e] = tanhf(acc);
    __syncthreads();
    float a0 = b1[e], a1 = 0.f;
#pragma unroll 8
    for (int f = 0; f < HID; f += 2) {
        a0 = fmaf(h0[f],     W1[f*EE + e],       a0);
        a1 = fmaf(h0[f + 1], W1[(f + 1)*EE + e], a1);
    }
    g_h[node*EE + e] = tanhf(a0 + a1);
}

// CSR build: single pass, fixed row bases.
__global__ void k_build_csr(const float* __restrict__ nbh) {
    int wrow = blockIdx.x * (blockDim.x >> 5) + (threadIdx.x >> 5);
    int lane = threadIdx.x & 31;
    if (wrow >= KK*BN) return;
    const float* row = nbh + (size_t)wrow * NN;
    int rbase = wrow * NN;
    unsigned lt = (1u << lane) - 1u;
    int off = 0;
#pragma unroll 4
    for (int j0 = 0; j0 < NN; j0 += 128) {
        float v0 = row[j0 + lane];
        float v1 = row[j0 + 32 + lane];
        float v2 = row[j0 + 64 + lane];
        float v3 = row[j0 + 96 + lane];
        unsigned b0 = __ballot_sync(0xffffffffu, v0 > 0.f);
        if (v0 > 0.f) g_col[rbase + off + __popc(b0 & lt)] = j0 + lane;
        off += __popc(b0);
        unsigned b1 = __ballot_sync(0xffffffffu, v1 > 0.f);
        if (v1 > 0.f) g_col[rbase + off + __popc(b1 & lt)] = j0 + 32 + lane;
        off += __popc(b1);
        unsigned b2 = __ballot_sync(0xffffffffu, v2 > 0.f);
        if (v2 > 0.f) g_col[rbase + off + __popc(b2 & lt)] = j0 + 64 + lane;
        off += __popc(b2);
        unsigned b3 = __ballot_sync(0xffffffffu, v3 > 0.f);
        if (v3 > 0.f) g_col[rbase + off + __popc(b3 & lt)] = j0 + 96 + lane;
        off += __popc(b3);
    }
    if (lane == 0) { g_rowptr[wrow] = rbase; g_deg[wrow] = off; }
}

// fused graph preprocessing: recip+indeg -> scan -> cscfill (grid barriers).
__global__ void __launch_bounds__(256) k_graph() {
    int gw = (blockIdx.x * 256 + threadIdx.x) >> 5;
    int lane = threadIdx.x & 31;
    int b = gw / NN;
    int n = gw - b*NN;
    int rbase = g_rowptr[gw];
    int deg = g_deg[gw];

    for (int idx = lane; idx < deg; idx += 32) {
        int j = g_col[rbase + idx];
        int jr = b*NN + j;
        int jb = g_rowptr[jr], dj = g_deg[jr];
        int lo = 0, hi = dj;
        while (lo < hi) { int mid = (lo + hi) >> 1; if (g_col[jb + mid] < n) lo = mid + 1; else hi = mid; }
        g_erecip[rbase + idx] = (lo < dj && g_col[jb + lo] == n) ? (jb + lo) : -1;
        atomicAdd(&g_indeg[jr], 1);
    }
    grid_barrier(1);

    if (blockIdx.x == 0) {
        __shared__ int ssum[256];
        int t = threadIdx.x;
        int base = t * 16;
        int v[16];
        int s = 0;
#pragma unroll
        for (int i = 0; i < 16; i++) { v[i] = s; s += g_indeg[base + i]; }
        ssum[t] = s; __syncthreads();
        for (int off = 1; off < 256; off <<= 1) {
            int x = (t >= off) ? ssum[t - off] : 0;
            __syncthreads();
            ssum[t] += x;
            __syncthreads();
        }
        int pre = (t == 0) ? 0 : ssum[t - 1];
#pragma unroll
        for (int i = 0; i < 16; i++) g_cscPtr[base + i] = pre + v[i];
        if (t == 255) g_cscPtr[BN] = ssum[255];
    }
    grid_barrier(2);

    for (int idx = lane; idx < deg; idx += 32) {
        int dst = b*NN + g_col[rbase + idx];
        int pos = g_cscPtr[dst] + atomicAdd(&g_cscFill[dst], 1);
        g_cscSrc[pos] = gw;
        g_cscEdge[pos] = rbase + idx;
    }
}

// z = h @ attn_W per head; s_src/s_dst; packed bf16 z write. block (128 thr) per node.
__global__ void k_z(const float* __restrict__ attn_W, const float* __restrict__ a_src,
                    const float* __restrict__ a_dst) {
    int node = blockIdx.x;
    int t = threadIdx.x;
    int head = t >> 6, e = t & 63, lane = t & 31;
    __shared__ float hs[EE];
    __shared__ float rs[2], rd[2];
    if (t < EE) hs[t] = g_h[node*EE + t];
    if (t < 2) { rs[t] = 0.f; rd[t] = 0.f; }
    __syncthreads();
    const float* W = attn_W + head*EE*EE;
    float a0 = 0.f, a1 = 0.f, a2 = 0.f, a3 = 0.f;
#pragma unroll 4
    for (int d = 0; d < EE; d += 4) {
        a0 = fmaf(hs[d],     W[d*EE + e],       a0);
        a1 = fmaf(hs[d + 1], W[(d + 1)*EE + e], a1);
        a2 = fmaf(hs[d + 2], W[(d + 2)*EE + e], a2);
        a3 = fmaf(hs[d + 3], W[(d + 3)*EE + e], a3);
    }
    float acc = (a0 + a1) + (a2 + a3);
    g_z[((size_t)head*BN + node)*EE + e] = acc;
    // packed write: even lane packs (acc_e, acc_{e+1}) -> uint2 component per head
    float accn = __shfl_down_sync(0xffffffffu, acc, 1);
    if (!(lane & 1)) {
        __nv_bfloat162 p = __floats2bfloat162_rn(acc, accn);
        unsigned* dst = reinterpret_cast<unsigned*>(&g_zp[node*32 + (e >> 1)]);
        dst[head] = *reinterpret_cast<unsigned*>(&p);
    }
    float vs = acc * a_src[head*EE + e];
    float vd = acc * a_dst[head*EE + e];
#pragma unroll
    for (int o = 16; o > 0; o >>= 1) {
        vs += __shfl_xor_sync(0xffffffffu, vs, o);
        vd += __shfl_xor_sync(0xffffffffu, vd, o);
    }
    if ((t & 31) == 0) { atomicAdd(&rs[head], vs); atomicAdd(&rd[head], vd); }
    __syncthreads();
    if (t < 2) { g_ssrc[t*BN + node] = rs[t]; g_sdst[t*BN + node] = rd[t]; }
}

// column means of z (deg-0 fallback). grid = HH*BB*16, block 64. low-contention atomics.
__global__ void k_zmean_acc() {
    int hb = blockIdx.x >> 4;
    int c = blockIdx.x & 15;
    int e = threadIdx.x;
    float acc = 0.f;
    for (int n = c*128; n < c*128 + 128; n++)
        acc += g_z[((size_t)hb*NN + n)*EE + e];
    atomicAdd(&g_zmean[hb*EE + e], acc * (1.0f / NN));
}

// sparse attention aggregation: one warp per (k,node), BOTH heads fused.
// smem-staged per-chunk weights; single LDG.64 per edge covers both heads.
__global__ void __launch_bounds__(256) k_agg() {
    __shared__ float2 sw[8][64];
    __shared__ int    smi[8][64];
    int wid = threadIdx.x >> 5;
    int lane = threadIdx.x & 31;
    int warp = blockIdx.x * 8 + wid;
    int k = warp / BN;
    int node = warp - k*BN;
    int b = node / NN;
    float ss0 = g_ssrc[node];
    float ss1 = g_ssrc[BN + node];
    const float* sd0 = g_sdst + b*NN;
    const float* sd1 = g_sdst + BN + b*NN;
    const uint2* zp = g_zp + (size_t)(b*NN)*32;
    int crow = k*BN + node;
    int rbase = g_rowptr[crow];
    int deg = g_deg[crow];
    float a00 = 0.f, a01 = 0.f, a10 = 0.f, a11 = 0.f, Z0 = 0.f, Z1 = 0.f;
    for (int base = 0; base < deg; base += 64) {
        int cnt = deg - base; if (cnt > 64) cnt = 64;
#pragma unroll
        for (int h = 0; h < 64; h += 32) {
            int idx = base + h + lane;
            if (idx < deg) {
                int m = __ldg(&g_col[rbase + idx]);
                float t0, t1;
                asm("tanh.approx.f32 %0, %1;" : "=f"(t0) : "f"(ss0 + sd0[m]));
                asm("tanh.approx.f32 %0, %1;" : "=f"(t1) : "f"(ss1 + sd1[m]));
                float w0 = __expf(t0);
                float w1 = __expf(t1);
                smi[wid][h + lane] = m;
                sw[wid][h + lane] = make_float2(w0, w1);
                Z0 += w0; Z1 += w1;
            }
        }
        __syncwarp();
#pragma unroll 4
        for (int j = 0; j < cnt; j++) {
            float2 w = sw[wid][j];
            int m = smi[wid][j];
            uint2 v = __ldg(&zp[(size_t)m*32 + lane]);
            float2 v0 = __bfloat1622float2(*reinterpret_cast<__nv_bfloat162*>(&v.x));
            float2 v1 = __bfloat1622float2(*reinterpret_cast<__nv_bfloat162*>(&v.y));
            a00 = fmaf(w.x, v0.x, a00);
            a01 = fmaf(w.x, v0.y, a01);
            a10 = fmaf(w.y, v1.x, a10);
            a11 = fmaf(w.y, v1.y, a11);
        }
        __syncwarp();
    }
#pragma unroll
    for (int o = 16; o > 0; o >>= 1) {
        Z0 += __shfl_xor_sync(0xffffffffu, Z0, o);
        Z1 += __shfl_xor_sync(0xffffffffu, Z1, o);
    }
    float2 o0, o1;
    if (deg > 0) {
        float i0 = 1.f / Z0, i1 = 1.f / Z1;
        o0 = make_float2(a00*i0, a01*i0);
        o1 = make_float2(a10*i1, a11*i1);
    } else {
        o0 = make_float2(g_zmean[b*EE + 2*lane],        g_zmean[b*EE + 2*lane + 1]);
        o1 = make_float2(g_zmean[(BB + b)*EE + 2*lane], g_zmean[(BB + b)*EE + 2*lane + 1]);
    }
    ((float2*)(g_aggp + (((size_t)0*BN + node)*KK + k)*EE))[lane] = o0;
    ((float2*)(g_aggp + (((size_t)1*BN + node)*KK + k)*EE))[lane] = o1;
}

// combine heads + neighborhood attention over k + GRU update. block (64 thr) per node.
__global__ void k_update(const float* __restrict__ nbr_q, const float* __restrict__ gru_W,
                         const float* __restrict__ gru_U, const float* __restrict__ gru_b) {
    int node = blockIdx.x;
    int e = threadIdx.x;
    __shared__ float a0[EE], a1[EE], hs[EE], nxt[EE], rh[EE];
    __shared__ float red[2];
    size_t i00 = (((size_t)0*BN + node)*KK + 0)*EE + e;
    size_t i01 = (((size_t)0*BN + node)*KK + 1)*EE + e;
    size_t i10 = (((size_t)1*BN + node)*KK + 0)*EE + e;
    size_t i11 = (((size_t)1*BN + node)*KK + 1)*EE + e;
    a0[e] = tanhf(0.5f*(g_aggp[i00] + g_aggp[i10]));
    a1[e] = tanhf(0.5f*(g_aggp[i01] + g_aggp[i11]));
    hs[e] = g_h[node*EE + e];
    if (e < 2) red[e] = 0.f;
    if (node == 0) {
        g_zmean[e] = 0.f; g_zmean[64 + e] = 0.f;
        g_zmean[128 + e] = 0.f; g_zmean[192 + e] = 0.f;
    }
    __syncthreads();
    float q = nbr_q[e];
    float v0 = a0[e]*q, v1 = a1[e]*q;
#pragma unroll
    for (int o = 16; o > 0; o >>= 1) {
        v0 += __shfl_xor_sync(0xffffffffu, v0, o);
        v1 += __shfl_xor_sync(0xffffffffu, v1, o);
    }
    if ((e & 31) == 0) { atomicAdd(&red[0], v0); atomicAdd(&red[1], v1); }
    __syncthreads();
    float t0 = tanhf(red[0]), t1 = tanhf(red[1]);
    float e0 = expf(t0), e1 = expf(t1);
    float inv = 1.f / (e0 + e1);
    nxt[e] = e0*inv*a0[e] + e1*inv*a1[e];
    __syncthreads();
    float sW0 = 0.f, sW1 = 0.f, sW2 = 0.f, sU0 = 0.f, sU1 = 0.f;
#pragma unroll 8
    for (int d = 0; d < EE; d++) {
        float nd = nxt[d], hd = hs[d];
        const float* Wr = gru_W + d*192;
        const float* Ur = gru_U + d*192;
        sW0 = fmaf(nd, Wr[e],       sW0);
        sW1 = fmaf(nd, Wr[e + 64],  sW1);
        sW2 = fmaf(nd, Wr[e + 128], sW2);
        sU0 = fmaf(hd, Ur[e],       sU0);
        sU1 = fmaf(hd, Ur[e + 64],  sU1);
    }
    float zg = 1.f / (1.f + expf(-(sW0 + sU0 + gru_b[e])));
    float r  = 1.f / (1.f + expf(-(sW1 + sU1 + gru_b[e + 64])));
    rh[e] = r * hs[e];
    __syncthreads();
    float sU2 = 0.f;
#pragma unroll 8
    for (int d = 0; d < EE; d++) sU2 = fmaf(rh[d], gru_U[d*192 + e + 128], sU2);
    float htl = tanhf(sW2 + sU2 + gru_b[e + 128]);
    g_h[node*EE + e] = (1.f - zg)*hs[e] + zg*htl;
}

// decoder + dual-var MLPs fused. block (64 thr) per node.
__global__ void k_decode(const float* __restrict__ dW0, const float* __restrict__ db0,
                         const float* __restrict__ dW1, const float* __restrict__ db1,
                         const float* __restrict__ uW0, const float* __restrict__ ub0,
                         const float* __restrict__ uW1, const float* __restrict__ ub1) {
    int node = blockIdx.x;
    int e = threadIdx.x;
    __shared__ float hs[EE];
    __shared__ float red[2];
    hs[e] = g_h[node*EE + e];
    if (e < 2) red[e] = 0.f;
    __syncthreads();
    float ad = db0[e], au = ub0[e];
#pragma unroll 8
    for (int d = 0; d < EE; d++) {
        float hd = hs[d];
        ad = fmaf(hd, dW0[d*64 + e], ad);
        au = fmaf(hd, uW0[d*64 + e], au);
    }
    float vd = tanhf(ad) * dW1[e];
    float vu = tanhf(au) * uW1[e];
#pragma unroll
    for (int o = 16; o > 0; o >>= 1) {
        vd += __shfl_xor_sync(0xffffffffu, vd, o);
        vu += __shfl_xor_sync(0xffffffffu, vu, o);
    }
    if ((e & 31) == 0) { atomicAdd(&red[0], vd); atomicAdd(&red[1], vu); }
    __syncthreads();
    if (e == 0) { g_nw[node] = red[0] + db1[0]; g_dv[node] = red[1] + ub1[0]; }
}

// mega-fused flow + dual section with full-grid phases.
__global__ void __launch_bounds__(256) k_flow(const float* __restrict__ demands,
                                              float* __restrict__ out) {
    int gw = (blockIdx.x * 256 + threadIdx.x) >> 5;
    int lane = threadIdx.x & 31;
    int b = gw / NN;
    int rbase = g_rowptr[gw];
    int deg = g_deg[gw];
    const float* nwb = g_nw + b*NN;

    if (deg > 0) {
        float mx = -3.0e38f;
        for (int idx = lane; idx < deg; idx += 32) mx = fmaxf(mx, nwb[g_col[rbase + idx]]);
#pragma unroll
        for (int o = 16; o > 0; o >>= 1) mx = fmaxf(mx, __shfl_xor_sync(0xffffffffu, mx, o));
        float sm = 0.f;
        for (int idx = lane; idx < deg; idx += 32) sm += expf(nwb[g_col[rbase + idx]] - mx);
#pragma unroll
        for (int o = 16; o > 0; o >>= 1) sm += __shfl_xor_sync(0xffffffffu, sm, o);
        float inv = 1.f / sm;
        for (int idx = lane; idx < deg; idx += 32)
            g_eprop[rbase + idx] = expf(nwb[g_col[rbase + idx]] - mx) * inv;
    }
    if (lane == 0) {
        float v = fmaxf(-demands[gw], 0.f);
        g_s0[gw] = v;
        if (deg == 0 && v != 0.f) atomicAdd(&g_emptyArr[b], v);
    }
    grid_barrier(10);

    int p0 = g_cscPtr[gw], p1 = g_cscPtr[gw + 1];
    for (int it = 0; it < 9; it++) {
        const float* sin  = (it & 1) ? g_s1 : g_s0;
        float*       sout = (it & 1) ? g_s0 : g_s1;
        float acc = 0.f;
        for (int q = p0 + lane; q < p1; q += 32)
            acc += g_eprop[g_cscEdge[q]] * __ldcg(&sin[g_cscSrc[q]]);
#pragma unroll
        for (int o = 16; o > 0; o >>= 1) acc += __shfl_xor_sync(0xffffffffu, acc, o);
        if (lane == 0) {
            float uni = __ldcg(&g_emptyArr[it*BB + b]) * (1.0f / NN);
            float sv = fmaxf(acc + uni - demands[gw], 0.f);
            sout[gw] = sv;
            if (deg == 0 && sv != 0.f) atomicAdd(&g_emptyArr[(it + 1)*BB + b], sv);
        }
        grid_barrier(11 + it);
    }

    const float* sfin = g_s1;
    float si = __ldcg(&sfin[gw]);
    float dvi = g_dv[gw];
    float facc = 0.f, dacc = 0.f;
    for (int idx = lane; idx < deg; idx += 32) {
        int e = rbase + idx;
        int j = g_col[e];
        int jg = b*NN + j;
        float f = g_eprop[e] * si;
        int rc = g_erecip[e];
        float frec = (rc >= 0) ? g_eprop[rc] * __ldcg(&sfin[jg])
                               : ((g_deg[jg] == 0) ? __ldcg(&sfin[jg]) * (1.0f / NN) : 0.f);
        float fl = f - fminf(f, frec);
        facc = fmaf(fl, fl, facc);
        float dd = dvi - g_dv[jg];
        float y = 0.f, m = 0.f;
#pragma unroll
        for (int itr = 0; itr < 10; itr++) {
            float g2 = 2.f*y - dd;
            m = 0.9f*m + g2;
            y = fmaxf(y - 0.1f*m, 0.f);
        }
        dacc += y*y - dd*y;
    }
#pragma unroll
    for (int o = 16; o > 0; o >>= 1) {
        facc += __shfl_xor_sync(0xffffffffu, facc, o);
        dacc += __shfl_xor_sync(0xffffffffu, dacc, o);
    }
    if (lane == 0) {
        if (deg == 0) facc += si * si * (1.0f / NN);
        atomicAdd(&g_accflow[b], (double)facc + (double)(dvi * demands[gw]));
        atomicAdd(&g_accdual[b], (double)dacc);
    }
    grid_barrier(30);

    if (blockIdx.x == 0 && threadIdx.x < BB) {
        double f = *((volatile double*)&g_accflow[threadIdx.x]);
        double d = *((volatile double*)&g_accdual[threadIdx.x]);
        out[threadIdx.x] = (float)(f - d);
    }
}

// ---------------------------------------------------------------------------------------
extern "C" void kernel_launch(void* const* d_in, const int* in_sizes, int n_in,
                              void* d_out, int out_size) {
    const float* node_features   = (const float*)d_in[0];
    const float* node_embeddings = (const float*)d_in[1];
    const float* demands = (const float*)d_in[2];
    const float* nbh     = (const float*)d_in[4];
    const float* enc_W0  = (const float*)d_in[5];
    const float* enc_b0  = (const float*)d_in[6];
    const float* enc_W1  = (const float*)d_in[7];
    const float* enc_b1  = (const float*)d_in[8];
    const float* attn_W  = (const float*)d_in[9];
    const float* a_src   = (const float*)d_in[10];
    const float* a_dst   = (const float*)d_in[11];
    const float* nbr_q   = (const float*)d_in[12];
    const float* gru_W   = (const float*)d_in[13];
    const float* gru_U   = (const float*)d_in[14];
    const float* gru_b   = (const float*)d_in[15];
    const float* dec_W0  = (const float*)d_in[16];
    const float* dec_b0  = (const float*)d_in[17];
    const float* dec_W1  = (const float*)d_in[18];
    const float* dec_b1  = (const float*)d_in[19];
    const float* dual_W0 = (const float*)d_in[20];
    const float* dual_b0 = (const float*)d_in[21];
    const float* dual_W1 = (const float*)d_in[22];
    const float* dual_b1 = (const float*)d_in[23];
    float* out = (float*)d_out;

    k_encoder<<<BN, 64>>>(node_embeddings, node_features, enc_W0, enc_b0, enc_W1, enc_b1);
    k_build_csr<<<(KK*BN)/8, 256>>>(nbh);
    k_graph<<<FLOW_GRID, 256>>>();

    for (int layer = 0; layer < 2; layer++) {
        k_z<<<BN, 128>>>(attn_W, a_src, a_dst);
        k_zmean_acc<<<HH*BB*16, 64>>>();
        k_agg<<<(KK*BN)/8, 256>>>();
        k_update<<<BN, 64>>>(nbr_q, gru_W, gru_U, gru_b);
    }

    k_decode<<<BN, 64>>>(dec_W0, dec_b0, dec_W1, dec_b1, dual_W0, dual_b0, dual_W1, dual_b1);
    k_flow<<<FLOW_GRID, 256>>>(demands, out);
}

// round 17
// speedup vs baseline: 1.3719x; 1.0492x over previous
#include <cuda_runtime.h>
#include <cuda_bf16.h>
#include <math.h>

// Problem constants (fixed instance)
#define BB 2
#define NN 2048
#define FEMB 16
#define FFEAT 2
#define FIN 18
#define EE 64
#define HH 2
#define KK 2
#define HID 64
#define BN (BB*NN)
#define FLOW_GRID 512

// ---------------- scratch (static device globals; no runtime allocation) ----------------
__device__ float g_h[BN*EE];                 // node hidden state
__device__ float g_z[HH*BN*EE];              // per-head projected features (fp32, zmean path)
__device__ __align__(16) uint2 g_zp[BN*32];  // packed bf16 z: per node 32x{head0 bf16x2, head1 bf16x2}
__device__ float g_ssrc[HH*BN];
__device__ float g_sdst[HH*BN];
__device__ float g_zmean[HH*BB*EE];          // fallback for empty neighbor rows
__device__ float g_aggp[HH*BN*KK*EE];        // per-head aggregation partials
__device__ int   g_rowptr[KK*BN];
__device__ int   g_deg[KK*BN];
__device__ int   g_col[KK*BN*NN];            // CSR col indices, fixed row*NN bases
__device__ float g_nw[BN];                   // decoder node weights
__device__ float g_dv[BN];                   // dual vars
__device__ float g_eprop[BN*NN];             // per-edge prop value (k=0 edge index space)
__device__ int   g_erecip[BN*NN];            // reciprocal edge index or -1
__device__ int   g_indeg[BN];
__device__ int   g_cscPtr[BN+1];
__device__ int   g_cscFill[BN];
__device__ int   g_cscSrc[BN*NN];            // src global row per in-edge
__device__ int   g_cscEdge[BN*NN];           // edge index per in-edge
__device__ float g_s0[BN], g_s1[BN];         // flow scalar ping-pong
__device__ float g_emptyArr[10*BB];          // uniform-mass scalar per iteration input
__device__ double g_accflow[BB], g_accdual[BB];

// software grid barrier state (reset by k_encoder each replay)
__device__ unsigned g_barCnt;
__device__ volatile unsigned g_barPhase;

__device__ __forceinline__ void grid_barrier(unsigned phase) {
    __syncthreads();
    if (threadIdx.x == 0) {
        __threadfence();
        if (atomicAdd(&g_barCnt, 1u) == gridDim.x - 1) {
            g_barCnt = 0;
            __threadfence();
            g_barPhase = phase;
        } else {
            while (g_barPhase < phase) {}
        }
        __threadfence();
    }
    __syncthreads();
}

// ---------------------------------------------------------------------------------------
// encoder + all per-replay zero-init. one block (64 thr) per 2 nodes; weight regs reused.
__global__ void k_encoder(const float* __restrict__ emb, const float* __restrict__ feat,
                          const float* __restrict__ W0, const float* __restrict__ b0,
                          const float* __restrict__ W1, const float* __restrict__ b1) {
    int node0 = blockIdx.x * 2;
    int e = threadIdx.x;
    if (e < 2) { g_indeg[node0 + e] = 0; g_cscFill[node0 + e] = 0; }
    if (node0 == 0) {
        g_zmean[e] = 0.f; g_zmean[64 + e] = 0.f;
        g_zmean[128 + e] = 0.f; g_zmean[192 + e] = 0.f;
        if (e < 10*BB) g_emptyArr[e] = 0.f;
        if (e < BB) { g_accflow[e] = 0.0; g_accdual[e] = 0.0; }
        if (e == 0) { g_barCnt = 0; g_barPhase = 0; }
    }
    __shared__ float x[2][FIN];
    __shared__ float h0[2][HID];
    if (e < FEMB) { x[0][e] = emb[node0*FEMB + e]; x[1][e] = emb[(node0+1)*FEMB + e]; }
    else if (e < FIN) {
        x[0][e] = feat[node0*FFEAT + (e - FEMB)];
        x[1][e] = feat[(node0+1)*FFEAT + (e - FEMB)];
    }
    __syncthreads();
    float ac0 = b0[e], ac1 = b0[e];
#pragma unroll
    for (int f = 0; f < FIN; f++) {
        float w = W0[f*HID + e];
        ac0 = fmaf(x[0][f], w, ac0);
        ac1 = fmaf(x[1][f], w, ac1);
    }
    h0[0][e] = tanhf(ac0);
    h0[1][e] = tanhf(ac1);
    __syncthreads();
    float b0v = b1[e];
    float s00 = 0.f, s01 = 0.f, s10 = 0.f, s11 = 0.f;
#pragma unroll 8
    for (int f = 0; f < HID; f += 2) {
        float w0 = W1[f*EE + e], w1 = W1[(f + 1)*EE + e];
        s00 = fmaf(h0[0][f],     w0, s00);
        s01 = fmaf(h0[0][f + 1], w1, s01);
        s10 = fmaf(h0[1][f],     w0, s10);
        s11 = fmaf(h0[1][f + 1], w1, s11);
    }
    g_h[node0*EE + e]       = tanhf(b0v + s00 + s01);
    g_h[(node0+1)*EE + e]   = tanhf(b0v + s10 + s11);
}

// CSR build: single pass, fixed row bases.
__global__ void k_build_csr(const float* __restrict__ nbh) {
    int wrow = blockIdx.x * (blockDim.x >> 5) + (threadIdx.x >> 5);
    int lane = threadIdx.x & 31;
    if (wrow >= KK*BN) return;
    const float* row = nbh + (size_t)wrow * NN;
    int rbase = wrow * NN;
    unsigned lt = (1u << lane) - 1u;
    int off = 0;
#pragma unroll 4
    for (int j0 = 0; j0 < NN; j0 += 128) {
        float v0 = row[j0 + lane];
        float v1 = row[j0 + 32 + lane];
        float v2 = row[j0 + 64 + lane];
        float v3 = row[j0 + 96 + lane];
        unsigned b0 = __ballot_sync(0xffffffffu, v0 > 0.f);
        if (v0 > 0.f) g_col[rbase + off + __popc(b0 & lt)] = j0 + lane;
        off += __popc(b0);
        unsigned b1 = __ballot_sync(0xffffffffu, v1 > 0.f);
        if (v1 > 0.f) g_col[rbase + off + __popc(b1 & lt)] = j0 + 32 + lane;
        off += __popc(b1);
        unsigned b2 = __ballot_sync(0xffffffffu, v2 > 0.f);
        if (v2 > 0.f) g_col[rbase + off + __popc(b2 & lt)] = j0 + 64 + lane;
        off += __popc(b2);
        unsigned b3 = __ballot_sync(0xffffffffu, v3 > 0.f);
        if (v3 > 0.f) g_col[rbase + off + __popc(b3 & lt)] = j0 + 96 + lane;
        off += __popc(b3);
    }
    if (lane == 0) { g_rowptr[wrow] = rbase; g_deg[wrow] = off; }
}

// fused graph preprocessing: recip+indeg -> scan -> cscfill (grid barriers).
__global__ void __launch_bounds__(256) k_graph() {
    int gw = (blockIdx.x * 256 + threadIdx.x) >> 5;
    int lane = threadIdx.x & 31;
    int b = gw / NN;
    int n = gw - b*NN;
    int rbase = g_rowptr[gw];
    int deg = g_deg[gw];

    for (int idx = lane; idx < deg; idx += 32) {
        int j = g_col[rbase + idx];
        int jr = b*NN + j;
        int jb = g_rowptr[jr], dj = g_deg[jr];
        int lo = 0, hi = dj;
        while (lo < hi) { int mid = (lo + hi) >> 1; if (g_col[jb + mid] < n) lo = mid + 1; else hi = mid; }
        g_erecip[rbase + idx] = (lo < dj && g_col[jb + lo] == n) ? (jb + lo) : -1;
        atomicAdd(&g_indeg[jr], 1);
    }
    grid_barrier(1);

    if (blockIdx.x == 0) {
        __shared__ int ssum[256];
        int t = threadIdx.x;
        int base = t * 16;
        int v[16];
        int s = 0;
#pragma unroll
        for (int i = 0; i < 16; i++) { v[i] = s; s += g_indeg[base + i]; }
        ssum[t] = s; __syncthreads();
        for (int off = 1; off < 256; off <<= 1) {
            int x = (t >= off) ? ssum[t - off] : 0;
            __syncthreads();
            ssum[t] += x;
            __syncthreads();
        }
        int pre = (t == 0) ? 0 : ssum[t - 1];
#pragma unroll
        for (int i = 0; i < 16; i++) g_cscPtr[base + i] = pre + v[i];
        if (t == 255) g_cscPtr[BN] = ssum[255];
    }
    grid_barrier(2);

    for (int idx = lane; idx < deg; idx += 32) {
        int dst = b*NN + g_col[rbase + idx];
        int pos = g_cscPtr[dst] + atomicAdd(&g_cscFill[dst], 1);
        g_cscSrc[pos] = gw;
        g_cscEdge[pos] = rbase + idx;
    }
}

// z = h @ attn_W per head for TWO nodes per block (weight regs reused).
__global__ void k_z(const float* __restrict__ attn_W, const float* __restrict__ a_src,
                    const float* __restrict__ a_dst) {
    int node0 = blockIdx.x * 2;
    int t = threadIdx.x;
    int head = t >> 6, e = t & 63, lane = t & 31;
    __shared__ float hs[2][EE];
    __shared__ float rs[2][2], rd[2][2];   // [node][head]
    if (t < EE) hs[0][t] = g_h[node0*EE + t];
    else        hs[1][t - EE] = g_h[(node0+1)*EE + (t - EE)];
    if (t < 4) { ((float*)rs)[t] = 0.f; ((float*)rd)[t] = 0.f; }
    __syncthreads();
    const float* W = attn_W + head*EE*EE;
    float s00 = 0.f, s01 = 0.f, s10 = 0.f, s11 = 0.f;
#pragma unroll 4
    for (int d = 0; d < EE; d += 2) {
        float w0 = W[d*EE + e], w1 = W[(d + 1)*EE + e];
        s00 = fmaf(hs[0][d],     w0, s00);
        s01 = fmaf(hs[0][d + 1], w1, s01);
        s10 = fmaf(hs[1][d],     w0, s10);
        s11 = fmaf(hs[1][d + 1], w1, s11);
    }
    float acc0 = s00 + s01;
    float acc1 = s10 + s11;
    g_z[((size_t)head*BN + node0)*EE + e]     = acc0;
    g_z[((size_t)head*BN + node0 + 1)*EE + e] = acc1;
    float acc0n = __shfl_down_sync(0xffffffffu, acc0, 1);
    float acc1n = __shfl_down_sync(0xffffffffu, acc1, 1);
    if (!(lane & 1)) {
        __nv_bfloat162 p0 = __floats2bfloat162_rn(acc0, acc0n);
        __nv_bfloat162 p1 = __floats2bfloat162_rn(acc1, acc1n);
        reinterpret_cast<unsigned*>(&g_zp[node0*32 + (e >> 1)])[head]     = *reinterpret_cast<unsigned*>(&p0);
        reinterpret_cast<unsigned*>(&g_zp[(node0+1)*32 + (e >> 1)])[head] = *reinterpret_cast<unsigned*>(&p1);
    }
    float as = a_src[head*EE + e], ad = a_dst[head*EE + e];
    float vs0 = acc0*as, vd0 = acc0*ad, vs1 = acc1*as, vd1 = acc1*ad;
#pragma unroll
    for (int o = 16; o > 0; o >>= 1) {
        vs0 += __shfl_xor_sync(0xffffffffu, vs0, o);
        vd0 += __shfl_xor_sync(0xffffffffu, vd0, o);
        vs1 += __shfl_xor_sync(0xffffffffu, vs1, o);
        vd1 += __shfl_xor_sync(0xffffffffu, vd1, o);
    }
    if (lane == 0) {
        atomicAdd(&rs[0][head], vs0); atomicAdd(&rd[0][head], vd0);
        atomicAdd(&rs[1][head], vs1); atomicAdd(&rd[1][head], vd1);
    }
    __syncthreads();
    if (t < 2) {
        g_ssrc[t*BN + node0] = rs[0][t];     g_sdst[t*BN + node0] = rd[0][t];
        g_ssrc[t*BN + node0 + 1] = rs[1][t]; g_sdst[t*BN + node0 + 1] = rd[1][t];
    }
}

// column means of z (deg-0 fallback). grid = HH*BB*16, block 64.
__global__ void k_zmean_acc() {
    int hb = blockIdx.x >> 4;
    int c = blockIdx.x & 15;
    int e = threadIdx.x;
    float acc = 0.f;
    for (int n = c*128; n < c*128 + 128; n++)
        acc += g_z[((size_t)hb*NN + n)*EE + e];
    atomicAdd(&g_zmean[hb*EE + e], acc * (1.0f / NN));
}

// sparse attention aggregation: one warp per (k,node), BOTH heads fused.
__global__ void __launch_bounds__(256) k_agg() {
    __shared__ float2 sw[8][64];
    __shared__ int    smi[8][64];
    int wid = threadIdx.x >> 5;
    int lane = threadIdx.x & 31;
    int warp = blockIdx.x * 8 + wid;
    int k = warp / BN;
    int node = warp - k*BN;
    int b = node / NN;
    float ss0 = g_ssrc[node];
    float ss1 = g_ssrc[BN + node];
    const float* sd0 = g_sdst + b*NN;
    const float* sd1 = g_sdst + BN + b*NN;
    const uint2* zp = g_zp + (size_t)(b*NN)*32;
    int crow = k*BN + node;
    int rbase = g_rowptr[crow];
    int deg = g_deg[crow];
    float a00 = 0.f, a01 = 0.f, a10 = 0.f, a11 = 0.f, Z0 = 0.f, Z1 = 0.f;
    for (int base = 0; base < deg; base += 64) {
        int cnt = deg - base; if (cnt > 64) cnt = 64;
#pragma unroll
        for (int h = 0; h < 64; h += 32) {
            int idx = base + h + lane;
            if (idx < deg) {
                int m = __ldg(&g_col[rbase + idx]);
                float t0, t1;
                asm("tanh.approx.f32 %0, %1;" : "=f"(t0) : "f"(ss0 + sd0[m]));
                asm("tanh.approx.f32 %0, %1;" : "=f"(t1) : "f"(ss1 + sd1[m]));
                float w0 = __expf(t0);
                float w1 = __expf(t1);
                smi[wid][h + lane] = m;
                sw[wid][h + lane] = make_float2(w0, w1);
                Z0 += w0; Z1 += w1;
            }
        }
        __syncwarp();
#pragma unroll 4
        for (int j = 0; j < cnt; j++) {
            float2 w = sw[wid][j];
            int m = smi[wid][j];
            uint2 v = __ldg(&zp[(size_t)m*32 + lane]);
            float2 v0 = __bfloat1622float2(*reinterpret_cast<__nv_bfloat162*>(&v.x));
            float2 v1 = __bfloat1622float2(*reinterpret_cast<__nv_bfloat162*>(&v.y));
            a00 = fmaf(w.x, v0.x, a00);
            a01 = fmaf(w.x, v0.y, a01);
            a10 = fmaf(w.y, v1.x, a10);
            a11 = fmaf(w.y, v1.y, a11);
        }
        __syncwarp();
    }
#pragma unroll
    for (int o = 16; o > 0; o >>= 1) {
        Z0 += __shfl_xor_sync(0xffffffffu, Z0, o);
        Z1 += __shfl_xor_sync(0xffffffffu, Z1, o);
    }
    float2 o0, o1;
    if (deg > 0) {
        float i0 = 1.f / Z0, i1 = 1.f / Z1;
        o0 = make_float2(a00*i0, a01*i0);
        o1 = make_float2(a10*i1, a11*i1);
    } else {
        o0 = make_float2(g_zmean[b*EE + 2*lane],        g_zmean[b*EE + 2*lane + 1]);
        o1 = make_float2(g_zmean[(BB + b)*EE + 2*lane], g_zmean[(BB + b)*EE + 2*lane + 1]);
    }
    ((float2*)(g_aggp + (((size_t)0*BN + node)*KK + k)*EE))[lane] = o0;
    ((float2*)(g_aggp + (((size_t)1*BN + node)*KK + k)*EE))[lane] = o1;
}

// combine heads + k-attention + GRU update for TWO nodes per block (weight regs reused).
__global__ void k_update(const float* __restrict__ nbr_q, const float* __restrict__ gru_W,
                         const float* __restrict__ gru_U, const float* __restrict__ gru_b) {
    int node0 = blockIdx.x * 2;
    int e = threadIdx.x;
    __shared__ float a0[2][EE], a1[2][EE], hs[2][EE], nxt[2][EE], rh[2][EE];
    __shared__ float red[2][2];
#pragma unroll
    for (int u = 0; u < 2; u++) {
        int node = node0 + u;
        size_t i00 = (((size_t)0*BN + node)*KK + 0)*EE + e;
        size_t i01 = (((size_t)0*BN + node)*KK + 1)*EE + e;
        size_t i10 = (((size_t)1*BN + node)*KK + 0)*EE + e;
        size_t i11 = (((size_t)1*BN + node)*KK + 1)*EE + e;
        a0[u][e] = tanhf(0.5f*(g_aggp[i00] + g_aggp[i10]));
        a1[u][e] = tanhf(0.5f*(g_aggp[i01] + g_aggp[i11]));
        hs[u][e] = g_h[node*EE + e];
    }
    if (e < 4) ((float*)red)[e] = 0.f;
    if (node0 == 0) {
        g_zmean[e] = 0.f; g_zmean[64 + e] = 0.f;
        g_zmean[128 + e] = 0.f; g_zmean[192 + e] = 0.f;
    }
    __syncthreads();
    float q = nbr_q[e];
    float v00 = a0[0][e]*q, v01 = a1[0][e]*q;
    float v10 = a0[1][e]*q, v11 = a1[1][e]*q;
#pragma unroll
    for (int o = 16; o > 0; o >>= 1) {
        v00 += __shfl_xor_sync(0xffffffffu, v00, o);
        v01 += __shfl_xor_sync(0xffffffffu, v01, o);
        v10 += __shfl_xor_sync(0xffffffffu, v10, o);
        v11 += __shfl_xor_sync(0xffffffffu, v11, o);
    }
    if ((e & 31) == 0) {
        atomicAdd(&red[0][0], v00); atomicAdd(&red[0][1], v01);
        atomicAdd(&red[1][0], v10); atomicAdd(&red[1][1], v11);
    }
    __syncthreads();
#pragma unroll
    for (int u = 0; u < 2; u++) {
        float t0 = tanhf(red[u][0]), t1 = tanhf(red[u][1]);
        float e0 = expf(t0), e1 = expf(t1);
        float inv = 1.f / (e0 + e1);
        nxt[u][e] = e0*inv*a0[u][e] + e1*inv*a1[u][e];
    }
    __syncthreads();
    float sW0[2] = {0.f, 0.f}, sW1[2] = {0.f, 0.f}, sW2[2] = {0.f, 0.f};
    float sU0[2] = {0.f, 0.f}, sU1[2] = {0.f, 0.f};
#pragma unroll 8
    for (int d = 0; d < EE; d++) {
        const float* Wr = gru_W + d*192;
        const float* Ur = gru_U + d*192;
        float w0 = Wr[e], w1 = Wr[e + 64], w2 = Wr[e + 128];
        float u0 = Ur[e], u1 = Ur[e + 64];
        float nd0 = nxt[0][d], nd1 = nxt[1][d];
        float hd0 = hs[0][d],  hd1 = hs[1][d];
        sW0[0] = fmaf(nd0, w0, sW0[0]); sW0[1] = fmaf(nd1, w0, sW0[1]);
        sW1[0] = fmaf(nd0, w1, sW1[0]); sW1[1] = fmaf(nd1, w1, sW1[1]);
        sW2[0] = fmaf(nd0, w2, sW2[0]); sW2[1] = fmaf(nd1, w2, sW2[1]);
        sU0[0] = fmaf(hd0, u0, sU0[0]); sU0[1] = fmaf(hd1, u0, sU0[1]);
        sU1[0] = fmaf(hd0, u1, sU1[0]); sU1[1] = fmaf(hd1, u1, sU1[1]);
    }
    float gb0 = gru_b[e], gb1 = gru_b[e + 64], gb2 = gru_b[e + 128];
    float zg[2], htW[2];
#pragma unroll
    for (int u = 0; u < 2; u++) {
        zg[u] = 1.f / (1.f + expf(-(sW0[u] + sU0[u] + gb0)));
        float r = 1.f / (1.f + expf(-(sW1[u] + sU1[u] + gb1)));
        rh[u][e] = r * hs[u][e];
        htW[u] = sW2[u];
    }
    __syncthreads();
    float sU2[2] = {0.f, 0.f};
#pragma unroll 8
    for (int d = 0; d < EE; d++) {
        float w = gru_U[d*192 + e + 128];
        sU2[0] = fmaf(rh[0][d], w, sU2[0]);
        sU2[1] = fmaf(rh[1][d], w, sU2[1]);
    }
#pragma unroll
    for (int u = 0; u < 2; u++) {
        float htl = tanhf(htW[u] + sU2[u] + gb2);
        g_h[(node0 + u)*EE + e] = (1.f - zg[u])*hs[u][e] + zg[u]*htl;
    }
}

// decoder + dual-var MLPs for TWO nodes per block.
__global__ void k_decode(const float* __restrict__ dW0, const float* __restrict__ db0,
                         const float* __restrict__ dW1, const float* __restrict__ db1,
                         const float* __restrict__ uW0, const float* __restrict__ ub0,
                         const float* __restrict__ uW1, const float* __restrict__ ub1) {
    int node0 = blockIdx.x * 2;
    int e = threadIdx.x;
    __shared__ float hs[2][EE];
    __shared__ float red[2][2];
    hs[0][e] = g_h[node0*EE + e];
    hs[1][e] = g_h[(node0+1)*EE + e];
    if (e < 4) ((float*)red)[e] = 0.f;
    __syncthreads();
    float ad0 = db0[e], au0 = ub0[e], ad1 = db0[e], au1 = ub0[e];
#pragma unroll 8
    for (int d = 0; d < EE; d++) {
        float wd = dW0[d*64 + e], wu = uW0[d*64 + e];
        float h0 = hs[0][d], h1 = hs[1][d];
        ad0 = fmaf(h0, wd, ad0); ad1 = fmaf(h1, wd, ad1);
        au0 = fmaf(h0, wu, au0); au1 = fmaf(h1, wu, au1);
    }
    float w1d = dW1[e], w1u = uW1[e];
    float vd0 = tanhf(ad0) * w1d, vu0 = tanhf(au0) * w1u;
    float vd1 = tanhf(ad1) * w1d, vu1 = tanhf(au1) * w1u;
#pragma unroll
    for (int o = 16; o > 0; o >>= 1) {
        vd0 += __shfl_xor_sync(0xffffffffu, vd0, o);
        vu0 += __shfl_xor_sync(0xffffffffu, vu0, o);
        vd1 += __shfl_xor_sync(0xffffffffu, vd1, o);
        vu1 += __shfl_xor_sync(0xffffffffu, vu1, o);
    }
    if ((e & 31) == 0) {
        atomicAdd(&red[0][0], vd0); atomicAdd(&red[0][1], vu0);
        atomicAdd(&red[1][0], vd1); atomicAdd(&red[1][1], vu1);
    }
    __syncthreads();
    if (e < 2) {
        g_nw[node0 + e] = red[e][0] + db1[0];
        g_dv[node0 + e] = red[e][1] + ub1[0];
    }
}

// mega-fused flow + dual section with full-grid phases.
__global__ void __launch_bounds__(256) k_flow(const float* __restrict__ demands,
                                              float* __restrict__ out) {
    int gw = (blockIdx.x * 256 + threadIdx.x) >> 5;
    int lane = threadIdx.x & 31;
    int b = gw / NN;
    int rbase = g_rowptr[gw];
    int deg = g_deg[gw];
    const float* nwb = g_nw + b*NN;

    if (deg > 0) {
        float mx = -3.0e38f;
        for (int idx = lane; idx < deg; idx += 32) mx = fmaxf(mx, nwb[g_col[rbase + idx]]);
#pragma unroll
        for (int o = 16; o > 0; o >>= 1) mx = fmaxf(mx, __shfl_xor_sync(0xffffffffu, mx, o));
        float sm = 0.f;
        for (int idx = lane; idx < deg; idx += 32) sm += expf(nwb[g_col[rbase + idx]] - mx);
#pragma unroll
        for (int o = 16; o > 0; o >>= 1) sm += __shfl_xor_sync(0xffffffffu, sm, o);
        float inv = 1.f / sm;
        for (int idx = lane; idx < deg; idx += 32)
            g_eprop[rbase + idx] = expf(nwb[g_col[rbase + idx]] - mx) * inv;
    }
    if (lane == 0) {
        float v = fmaxf(-demands[gw], 0.f);
        g_s0[gw] = v;
        if (deg == 0 && v != 0.f) atomicAdd(&g_emptyArr[b], v);
    }
    grid_barrier(10);

    int p0 = g_cscPtr[gw], p1 = g_cscPtr[gw + 1];
    for (int it = 0; it < 9; it++) {
        const float* sin  = (it & 1) ? g_s1 : g_s0;
        float*       sout = (it & 1) ? g_s0 : g_s1;
        float acc = 0.f;
        for (int q = p0 + lane; q < p1; q += 32)
            acc += g_eprop[g_cscEdge[q]] * __ldcg(&sin[g_cscSrc[q]]);
#pragma unroll
        for (int o = 16; o > 0; o >>= 1) acc += __shfl_xor_sync(0xffffffffu, acc, o);
        if (lane == 0) {
            float uni = __ldcg(&g_emptyArr[it*BB + b]) * (1.0f / NN);
            float sv = fmaxf(acc + uni - demands[gw], 0.f);
            sout[gw] = sv;
            if (deg == 0 && sv != 0.f) atomicAdd(&g_emptyArr[(it + 1)*BB + b], sv);
        }
        grid_barrier(11 + it);
    }

    const float* sfin = g_s1;
    float si = __ldcg(&sfin[gw]);
    float dvi = g_dv[gw];
    float facc = 0.f, dacc = 0.f;
    for (int idx = lane; idx < deg; idx += 32) {
        int e = rbase + idx;
        int j = g_col[e];
        int jg = b*NN + j;
        float f = g_eprop[e] * si;
        int rc = g_erecip[e];
        float frec = (rc >= 0) ? g_eprop[rc] * __ldcg(&sfin[jg])
                               : ((g_deg[jg] == 0) ? __ldcg(&sfin[jg]) * (1.0f / NN) : 0.f);
        float fl = f - fminf(f, frec);
        facc = fmaf(fl, fl, facc);
        float dd = dvi - g_dv[jg];
        float y = 0.f, m = 0.f;
#pragma unroll
        for (int itr = 0; itr < 10; itr++) {
            float g2 = 2.f*y - dd;
            m = 0.9f*m + g2;
            y = fmaxf(y - 0.1f*m, 0.f);
        }
        dacc += y*y - dd*y;
    }
#pragma unroll
    for (int o = 16; o > 0; o >>= 1) {
        facc += __shfl_xor_sync(0xffffffffu, facc, o);
        dacc += __shfl_xor_sync(0xffffffffu, dacc, o);
    }
    if (lane == 0) {
        if (deg == 0) facc += si * si * (1.0f / NN);
        atomicAdd(&g_accflow[b], (double)facc + (double)(dvi * demands[gw]));
        atomicAdd(&g_accdual[b], (double)dacc);
    }
    grid_barrier(30);

    if (blockIdx.x == 0 && threadIdx.x < BB) {
        double f = *((volatile double*)&g_accflow[threadIdx.x]);
        double d = *((volatile double*)&g_accdual[threadIdx.x]);
        out[threadIdx.x] = (float)(f - d);
    }
}

// ---------------------------------------------------------------------------------------
extern "C" void kernel_launch(void* const* d_in, const int* in_sizes, int n_in,
                              void* d_out, int out_size) {
    const float* node_features   = (const float*)d_in[0];
    const float* node_embeddings = (const float*)d_in[1];
    const float* demands = (const float*)d_in[2];
    const float* nbh     = (const float*)d_in[4];
    const float* enc_W0  = (const float*)d_in[5];
    const float* enc_b0  = (const float*)d_in[6];
    const float* enc_W1  = (const float*)d_in[7];
    const float* enc_b1  = (const float*)d_in[8];
    const float* attn_W  = (const float*)d_in[9];
    const float* a_src   = (const float*)d_in[10];
    const float* a_dst   = (const float*)d_in[11];
    const float* nbr_q   = (const float*)d_in[12];
    const float* gru_W   = (const float*)d_in[13];
    const float* gru_U   = (const float*)d_in[14];
    const float* gru_b   = (const float*)d_in[15];
    const float* dec_W0  = (const float*)d_in[16];
    const float* dec_b0  = (const float*)d_in[17];
    const float* dec_W1  = (const float*)d_in[18];
    const float* dec_b1  = (const float*)d_in[19];
    const float* dual_W0 = (const float*)d_in[20];
    const float* dual_b0 = (const float*)d_in[21];
    const float* dual_W1 = (const float*)d_in[22];
    const float* dual_b1 = (const float*)d_in[23];
    float* out = (float*)d_out;

    k_encoder<<<BN/2, 64>>>(node_embeddings, node_features, enc_W0, enc_b0, enc_W1, enc_b1);
    k_build_csr<<<(KK*BN)/8, 256>>>(nbh);
    k_graph<<<FLOW_GRID, 256>>>();

    for (int layer = 0; layer < 2; layer++) {
        k_z<<<BN/2, 128>>>(attn_W, a_src, a_dst);
        k_zmean_acc<<<HH*BB*16, 64>>>();
        k_agg<<<(KK*BN)/8, 256>>>();
        k_update<<<BN/2, 64>>>(nbr_q, gru_W, gru_U, gru_b);
    }

    k_decode<<<BN/2, 64>>>(dec_W0, dec_b0, dec_W1, dec_b1, dual_W0, dual_b0, dual_W1, dual_b1);
    k_flow<<<FLOW_GRID, 256>>>(demands, out);
}